// round 12
// baseline (speedup 1.0000x reference)
#include <cuda_runtime.h>
#include <cuda_fp16.h>
#include <cstdint>

#define BB 8
#define NN 4096
#define DD 128
#define SCALE 0.08838834764831845f
#define LOG2E 1.4426950408889634f
#define QS (SCALE * LOG2E)

#define BM 64
#define BN 64
#define NT (NN / BN)

typedef unsigned long long u64;

// scratch (no cudaMalloc allowed)
__device__ __half g_kh[(size_t)BB * NN * DD];
__device__ __half g_vh[(size_t)BB * NN * DD];
__device__ __half g_qh[(size_t)BB * NN * DD];

// ---- attention smem (bytes), BM=64. pitch 136 halves (272B); P pitch 72 ----
// K resident | QP shared (Q pitch136 / P pitch72 time-shared) | V single | lsum
// epilogue: Onorm fp16 -> K region; Wp fp16 -> QP..V contiguous (34816 B)
#define SM_K   0
#define SM_QP  17408
#define SM_V   34816
#define SM_LS  52224
#define SM_TOT 52736

// ---- PTX helpers ----
__device__ __forceinline__ uint32_t smem_u32(const void* p) {
    uint32_t a;
    asm("{ .reg .u64 t; cvta.to.shared.u64 t,%1; cvt.u32.u64 %0,t; }" : "=r"(a) : "l"(p));
    return a;
}
__device__ __forceinline__ void ldsmx4(uint32_t* r, uint32_t a) {
    asm volatile("ldmatrix.sync.aligned.m8n8.x4.shared.b16 {%0,%1,%2,%3},[%4];"
                 : "=r"(r[0]), "=r"(r[1]), "=r"(r[2]), "=r"(r[3]) : "r"(a));
}
__device__ __forceinline__ void ldsmx4t(uint32_t* r, uint32_t a) {
    asm volatile("ldmatrix.sync.aligned.m8n8.x4.trans.shared.b16 {%0,%1,%2,%3},[%4];"
                 : "=r"(r[0]), "=r"(r[1]), "=r"(r[2]), "=r"(r[3]) : "r"(a));
}
__device__ __forceinline__ void mma16816(float* c, const uint32_t* a, uint32_t b0, uint32_t b1) {
    asm volatile(
        "mma.sync.aligned.m16n8k16.row.col.f32.f16.f16.f32 "
        "{%0,%1,%2,%3},{%4,%5,%6,%7},{%8,%9},{%0,%1,%2,%3};"
        : "+f"(c[0]), "+f"(c[1]), "+f"(c[2]), "+f"(c[3])
        : "r"(a[0]), "r"(a[1]), "r"(a[2]), "r"(a[3]), "r"(b0), "r"(b1));
}
__device__ __forceinline__ float ex2(float x) {
    float y; asm("ex2.approx.f32 %0,%1;" : "=f"(y) : "f"(x)); return y;
}
__device__ __forceinline__ uint32_t packh2(float lo, float hi) {  // lo -> bits[0:16)
    uint32_t r; asm("cvt.rn.f16x2.f32 %0,%1,%2;" : "=r"(r) : "f"(hi), "f"(lo)); return r;
}
#define CPA16(dst, src) \
    asm volatile("cp.async.cg.shared.global [%0],[%1],16;" :: "r"(dst), "l"(src))
#define CPA_COMMIT() asm volatile("cp.async.commit_group;" ::: "memory")
#define CPA_WAIT0()  asm volatile("cp.async.wait_group 0;" ::: "memory")

// ============================================================================
// Attention + fused output projection. BM=64, 4 warps, 4 CTAs/SM.
// Per tile: S(jt) | sync | P->QP | sync | PV(jt) | sync | cp.async QV(jt+1)
//           | wait | sync
// ============================================================================
__global__ void __launch_bounds__(128, 4)
attn_mma(const __half* __restrict__ khg, const __half* __restrict__ vhg,
         const __half* __restrict__ qhg, const float* __restrict__ Wp,
         const float* __restrict__ bp, float* __restrict__ out) {
    extern __shared__ char smem[];
    const uint32_t sb = smem_u32(smem);
    const int tid = threadIdx.x, lane = tid & 31, wid = tid >> 5;
    const int q = lane & 3, lr = lane >> 2;
    const int b = blockIdx.y, row0 = blockIdx.x * BM;

    const __half* kh_b = khg + ((size_t)b * NN + row0) * DD;
    const __half* vh_b = vhg + (size_t)b * NN * DD;
    const __half* qh_b = qhg + (size_t)b * NN * DD;

    const int rg = wid >> 1, cg = wid & 1;   // 2x2 warp grid for both S and PV

    const int rA = (lane & 7) + (lane & 8), cA = (lane & 16) >> 1;   // A/P/V pattern
    const int rB = (lane & 7) + ((lane & 16) >> 1), cB = lane & 8;   // B (Q) pattern

    // ldmatrix bases
    uint32_t aK[2], bQ[2], aP[2], bV[4];
    #pragma unroll
    for (int mt = 0; mt < 2; ++mt) {
        aK[mt] = sb + SM_K  + 2u * ((32 * rg + 16 * mt + rA) * 136 + cA);
        aP[mt] = sb + SM_QP + 2u * ((32 * rg + 16 * mt + rA) * 72 + cA);
    }
    #pragma unroll
    for (int bt = 0; bt < 2; ++bt)
        bQ[bt] = sb + SM_QP + 2u * ((32 * cg + 16 * bt + rB) * 136 + cB);
    #pragma unroll
    for (int bt = 0; bt < 4; ++bt)
        bV[bt] = sb + SM_V + 2u * (rA * 136 + 64 * cg + 16 * bt + cA);

    // stage K tile (resident during main loop): 64 rows x 16 chunks of 16B
    #pragma unroll
    for (int t = 0; t < 8; ++t) {
        int c = tid + (t << 7);
        int r = c >> 4, c16 = c & 15;
        *(uint4*)(smem + SM_K + (uint32_t)(r * 272 + c16 * 16)) =
            *(const uint4*)((const char*)(kh_b + (size_t)r * DD) + c16 * 16);
    }
    // prefetch tile 0 (Q -> QP, V)
    #pragma unroll
    for (int t = 0; t < 8; ++t) {
        int c = tid + (t << 7);
        int m = c >> 4, c16 = c & 15;
        uint32_t dof = (uint32_t)(m * 272 + c16 * 16);
        CPA16(sb + SM_QP + dof, (const char*)(qh_b + (size_t)m * DD) + c16 * 16);
        CPA16(sb + SM_V + dof, (const char*)(vh_b + (size_t)m * DD) + c16 * 16);
    }
    CPA_COMMIT();
    CPA_WAIT0();
    __syncthreads();   // K + Q(0) + V(0) visible

    float sO[2][8][4];   // 32 rows x 64 cols per warp (d-half cg)
    #pragma unroll
    for (int i = 0; i < 2; ++i)
        #pragma unroll
        for (int j = 0; j < 8; ++j) {
            sO[i][j][0] = 0.f; sO[i][j][1] = 0.f; sO[i][j][2] = 0.f; sO[i][j][3] = 0.f;
        }
    float lloc[4] = {0.f, 0.f, 0.f, 0.f};

    for (int jt = 0; jt < NT; ++jt) {
        // ---- S(jt) = K @ Q^T : 32x32 warp tile, 8 k-steps ----
        float sC[2][4][4];
        #pragma unroll
        for (int i = 0; i < 2; ++i)
            #pragma unroll
            for (int j = 0; j < 4; ++j) {
                sC[i][j][0] = 0.f; sC[i][j][1] = 0.f; sC[i][j][2] = 0.f; sC[i][j][3] = 0.f;
            }
        #pragma unroll
        for (int ks = 0; ks < 8; ++ks) {
            uint32_t kf[2][4], qf[2][4];
            #pragma unroll
            for (int mt = 0; mt < 2; ++mt) ldsmx4(kf[mt], aK[mt] + ks * 32);
            #pragma unroll
            for (int bt = 0; bt < 2; ++bt) ldsmx4(qf[bt], bQ[bt] + ks * 32);
            #pragma unroll
            for (int mt = 0; mt < 2; ++mt)
                #pragma unroll
                for (int nt = 0; nt < 4; ++nt)
                    mma16816(sC[mt][nt], kf[mt],
                             qf[nt >> 1][2 * (nt & 1)], qf[nt >> 1][2 * (nt & 1) + 1]);
        }
        __syncthreads();   // Q(jt) consumed by all -> QP free for P

        // ---- P(jt) = exp2(S) fp16 -> QP (pitch 72); accumulate row sums ----
        #pragma unroll
        for (int mt = 0; mt < 2; ++mt) {
            int rbase = 32 * rg + 16 * mt + lr;
            #pragma unroll
            for (int nt = 0; nt < 4; ++nt) {
                int col = 32 * cg + 8 * nt + 2 * q;
                float p0 = ex2(sC[mt][nt][0]), p1 = ex2(sC[mt][nt][1]);
                float p2 = ex2(sC[mt][nt][2]), p3 = ex2(sC[mt][nt][3]);
                lloc[2 * mt] += p0 + p1;
                lloc[2 * mt + 1] += p2 + p3;
                *(uint32_t*)(smem + SM_QP + 2u * (rbase * 72 + col)) = packh2(p0, p1);
                *(uint32_t*)(smem + SM_QP + 2u * ((rbase + 8) * 72 + col)) = packh2(p2, p3);
            }
        }
        __syncthreads();   // P visible

        // ---- PV(jt): O += P @ V : 32 rows x 64 cols per warp, 4 k-steps ----
        #pragma unroll
        for (int ks = 0; ks < 4; ++ks) {
            uint32_t ph[2][4], vf[4][4];
            #pragma unroll
            for (int mt = 0; mt < 2; ++mt) ldsmx4(ph[mt], aP[mt] + ks * 32);
            #pragma unroll
            for (int bt = 0; bt < 4; ++bt) ldsmx4t(vf[bt], bV[bt] + ks * 4352);
            #pragma unroll
            for (int mt = 0; mt < 2; ++mt)
                #pragma unroll
                for (int nt = 0; nt < 8; ++nt)
                    mma16816(sO[mt][nt], ph[mt],
                             vf[nt >> 1][2 * (nt & 1)], vf[nt >> 1][2 * (nt & 1) + 1]);
        }
        __syncthreads();   // PV done in all warps: QP + V free

        // ---- prefetch Q(jt+1) -> QP, V(jt+1) -> V ----
        if (jt + 1 < NT) {
            const size_t m1 = (size_t)(jt + 1) * BN;
            #pragma unroll
            for (int t = 0; t < 8; ++t) {
                int c = tid + (t << 7);
                int m = c >> 4, c16 = c & 15;
                uint32_t dof = (uint32_t)(m * 272 + c16 * 16);
                CPA16(sb + SM_QP + dof, (const char*)(qh_b + (m1 + m) * DD) + c16 * 16);
                CPA16(sb + SM_V + dof, (const char*)(vh_b + (m1 + m) * DD) + c16 * 16);
            }
            CPA_COMMIT();
            CPA_WAIT0();
            __syncthreads();   // QV(jt+1) visible
        }
    }

    // ---- l reduction: quad shfl + cross-colgroup via smem ----
    #pragma unroll
    for (int i = 0; i < 4; ++i) {
        lloc[i] += __shfl_xor_sync(0xffffffffu, lloc[i], 1);
        lloc[i] += __shfl_xor_sync(0xffffffffu, lloc[i], 2);
    }
    float* lsum = (float*)(smem + SM_LS);
    if (q == 0) {
        #pragma unroll
        for (int i = 0; i < 4; ++i) {
            int row = 32 * rg + 16 * (i >> 1) + 8 * (i & 1) + lr;
            lsum[cg * 64 + row] = lloc[i];
        }
    }
    __syncthreads();

    // ---- epilogue part 1: O/l -> fp16 into SM_K (pitch 136) ----
    #pragma unroll
    for (int mt = 0; mt < 2; ++mt) {
        int ra = 32 * rg + 16 * mt + lr;
        float inva = 1.0f / (lsum[ra] + lsum[64 + ra]);
        float invb = 1.0f / (lsum[ra + 8] + lsum[64 + ra + 8]);
        #pragma unroll
        for (int nt = 0; nt < 8; ++nt) {
            int col = 64 * cg + 8 * nt + 2 * q;
            *(uint32_t*)(smem + SM_K + 2u * (ra * 136 + col)) =
                packh2(sO[mt][nt][0] * inva, sO[mt][nt][1] * inva);
            *(uint32_t*)(smem + SM_K + 2u * ((ra + 8) * 136 + col)) =
                packh2(sO[mt][nt][2] * invb, sO[mt][nt][3] * invb);
        }
    }
    // Wp fp32 -> fp16 (pitch 136) into QP..V contiguous region (34816 B)
    #pragma unroll
    for (int t = 0; t < 16; ++t) {
        int c = tid + (t << 7);
        int k = c >> 4, c16 = c & 15;
        float4 v0 = *(const float4*)(Wp + (size_t)k * 128 + c16 * 8);
        float4 v1 = *(const float4*)(Wp + (size_t)k * 128 + c16 * 8 + 4);
        uint4 h;
        h.x = packh2(v0.x, v0.y); h.y = packh2(v0.z, v0.w);
        h.z = packh2(v1.x, v1.y); h.w = packh2(v1.z, v1.w);
        *(uint4*)(smem + SM_QP + (uint32_t)(k * 272 + c16 * 16)) = h;
    }
    __syncthreads();

    // ---- epilogue part 2: out = Onorm @ Wp + bp (64x128, warp = 32 n-cols) ----
    {
        uint32_t aB[4], bB[2];
        #pragma unroll
        for (int mt = 0; mt < 4; ++mt)
            aB[mt] = sb + SM_K + 2u * ((16 * mt + rA) * 136 + cA);
        #pragma unroll
        for (int bt = 0; bt < 2; ++bt)
            bB[bt] = sb + SM_QP + 2u * (rA * 136 + 32 * wid + 16 * bt + cA);

        float acc[4][4][4];
        #pragma unroll
        for (int i = 0; i < 4; ++i)
            #pragma unroll
            for (int j = 0; j < 4; ++j) {
                acc[i][j][0] = 0.f; acc[i][j][1] = 0.f; acc[i][j][2] = 0.f; acc[i][j][3] = 0.f;
            }
        #pragma unroll
        for (int ks = 0; ks < 8; ++ks) {
            uint32_t a[4][4], bf[2][4];
            #pragma unroll
            for (int mt = 0; mt < 4; ++mt) ldsmx4(a[mt], aB[mt] + ks * 32);
            #pragma unroll
            for (int bt = 0; bt < 2; ++bt) ldsmx4t(bf[bt], bB[bt] + ks * 4352);
            #pragma unroll
            for (int mt = 0; mt < 4; ++mt)
                #pragma unroll
                for (int nt = 0; nt < 4; ++nt)
                    mma16816(acc[mt][nt], a[mt],
                             bf[nt >> 1][2 * (nt & 1)], bf[nt >> 1][2 * (nt & 1) + 1]);
        }

        float* ob = out + ((size_t)b * NN + row0) * DD;
        #pragma unroll
        for (int mt = 0; mt < 4; ++mt) {
            int ra = 16 * mt + lr;
            #pragma unroll
            for (int nt = 0; nt < 4; ++nt) {
                int col = 32 * wid + 8 * nt + 2 * q;
                float b0 = bp[col], b1 = bp[col + 1];
                *(float2*)(ob + (size_t)ra * DD + col) =
                    make_float2(acc[mt][nt][0] + b0, acc[mt][nt][1] + b1);
                *(float2*)(ob + (size_t)(ra + 8) * DD + col) =
                    make_float2(acc[mt][nt][2] + b0, acc[mt][nt][3] + b1);
            }
        }
    }
}

// ============================================================================
// fp16 tensor-core kv projection (128x128 CTA tile) + fused Q conversion
// grid (3, M/128): x in {0,1} -> kv cols; x==2 -> Q fp32->fp16 (scaled)
// ============================================================================
__device__ __forceinline__ uint32_t pack_us2(__half a, __half b) {
    return (uint32_t)__half_as_ushort(a) | ((uint32_t)__half_as_ushort(b) << 16);
}

__global__ void __launch_bounds__(256, 2)
gemm16_kv(const float* __restrict__ A, const float* __restrict__ W,
          const float* __restrict__ bias, const float* __restrict__ qg,
          __half* __restrict__ kh, __half* __restrict__ vh,
          __half* __restrict__ qh) {
    if (blockIdx.x == 2) {   // fused qconv: 128 rows of Q per y-block
        const size_t base = (size_t)blockIdx.y * (128 * 128 / 4);
        const float4* src = (const float4*)qg + base;
        __half2* dst = (__half2*)qh + base * 2;
        #pragma unroll
        for (int t = 0; t < 16; ++t) {
            int f = threadIdx.x + (t << 8);
            float4 v = src[f];
            dst[2 * f]     = __floats2half2_rn(v.x * QS, v.y * QS);
            dst[2 * f + 1] = __floats2half2_rn(v.z * QS, v.w * QS);
        }
        return;
    }

    extern __shared__ char smg[];
    const uint32_t sb = smem_u32(smg);
    const int tid = threadIdx.x, lane = tid & 31, wid = tid >> 5;
    const int q = lane & 3, lr = lane >> 2;
    const int rw = wid >> 2, cw = wid & 3;
    const int row0 = blockIdx.y * 128, col0 = blockIdx.x * 128;

    #pragma unroll
    for (int it = 0; it < 16; ++it) {
        int f = tid + (it << 8);
        int r = f >> 5, c4 = f & 31;
        float4 v = *(const float4*)(A + (size_t)(row0 + r) * 128 + (c4 << 2));
        uint2 h; h.x = packh2(v.x, v.y); h.y = packh2(v.z, v.w);
        *(uint2*)(smg + (uint32_t)(r * 272 + (c4 << 3))) = h;
    }
    #pragma unroll
    for (int it = 0; it < 16; ++it) {
        int f = tid + (it << 8);
        int k = f >> 5, c4 = f & 31;
        float4 v = *(const float4*)(W + (size_t)k * 256 + col0 + (c4 << 2));
        uint2 h; h.x = packh2(v.x, v.y); h.y = packh2(v.z, v.w);
        *(uint2*)(smg + 34816 + (uint32_t)(k * 272 + (c4 << 3))) = h;
    }
    __syncthreads();

    const int rA = (lane & 7) + (lane & 8), cA = (lane & 16) >> 1;
    uint32_t aBase[4], bBase[2];
    #pragma unroll
    for (int mt = 0; mt < 4; ++mt)
        aBase[mt] = sb + 2u * ((64 * rw + 16 * mt + rA) * 136 + cA);
    #pragma unroll
    for (int bt = 0; bt < 2; ++bt)
        bBase[bt] = sb + 34816 + 2u * (rA * 136 + 32 * cw + 16 * bt + cA);

    float acc[4][4][4];
    #pragma unroll
    for (int i = 0; i < 4; ++i)
        #pragma unroll
        for (int j = 0; j < 4; ++j) {
            acc[i][j][0] = 0.f; acc[i][j][1] = 0.f; acc[i][j][2] = 0.f; acc[i][j][3] = 0.f;
        }
    #pragma unroll
    for (int ks = 0; ks < 8; ++ks) {
        uint32_t a[4][4], bf[2][4];
        #pragma unroll
        for (int mt = 0; mt < 4; ++mt) ldsmx4(a[mt], aBase[mt] + ks * 32);
        #pragma unroll
        for (int bt = 0; bt < 2; ++bt) ldsmx4t(bf[bt], bBase[bt] + ks * 4352);
        #pragma unroll
        for (int mt = 0; mt < 4; ++mt)
            #pragma unroll
            for (int nt = 0; nt < 4; ++nt)
                mma16816(acc[mt][nt], a[mt],
                         bf[nt >> 1][2 * (nt & 1)], bf[nt >> 1][2 * (nt & 1) + 1]);
    }

    __half* dh = (col0 == 0) ? kh : vh;
    #pragma unroll
    for (int mt = 0; mt < 4; ++mt) {
        int r = row0 + 64 * rw + 16 * mt + lr;
        #pragma unroll
        for (int nt = 0; nt < 4; ++nt) {
            int col = 32 * cw + 8 * nt + 2 * q;
            float b0 = bias[col0 + col], b1 = bias[col0 + col + 1];
            *(uint32_t*)(dh + (size_t)r * 128 + col) = pack_us2(
                __float2half_rn(acc[mt][nt][0] + b0), __float2half_rn(acc[mt][nt][1] + b1));
            *(uint32_t*)(dh + (size_t)(r + 8) * 128 + col) = pack_us2(
                __float2half_rn(acc[mt][nt][2] + b0), __float2half_rn(acc[mt][nt][3] + b1));
        }
    }
}

// ============================================================================
extern "C" void kernel_launch(void* const* d_in, const int* in_sizes, int n_in,
                              void* d_out, int out_size) {
    const float* x   = (const float*)d_in[0];
    const float* qg  = (const float*)d_in[1];
    const float* Wkv = (const float*)d_in[2];
    const float* bkv = (const float*)d_in[3];
    const float* Wp  = (const float*)d_in[4];
    const float* bp  = (const float*)d_in[5];
    float* out = (float*)d_out;

    __half *khp, *vhp, *qhp;
    cudaGetSymbolAddress((void**)&khp, g_kh);
    cudaGetSymbolAddress((void**)&vhp, g_vh);
    cudaGetSymbolAddress((void**)&qhp, g_qh);

    const int M = BB * NN;
    const int gsm = 2 * 128 * 272;  // 69632 B

    cudaFuncSetAttribute(gemm16_kv,
                         cudaFuncAttributeMaxDynamicSharedMemorySize, gsm);
    cudaFuncSetAttribute(attn_mma,
                         cudaFuncAttributeMaxDynamicSharedMemorySize, SM_TOT);

    gemm16_kv<<<dim3(3, M / 128), 256, gsm>>>(x, Wkv, bkv, qg, khp, vhp, qhp);
    attn_mma<<<dim3(NN / BM, BB), 128, SM_TOT>>>(khp, vhp, qhp, Wp, bp, out);
}

// round 13
// speedup vs baseline: 1.7241x; 1.7241x over previous
#include <cuda_runtime.h>
#include <cuda_fp16.h>
#include <cstdint>

#define BB 8
#define NN 4096
#define DD 128
#define SCALE 0.08838834764831845f
#define LOG2E 1.4426950408889634f
#define QS (SCALE * LOG2E)

#define BM 128
#define BN 64
#define NT (NN / BN)

typedef unsigned long long u64;

// scratch (no cudaMalloc allowed)
__device__ __half g_kh[(size_t)BB * NN * DD];
__device__ __half g_vh[(size_t)BB * NN * DD];
__device__ __half g_qh[(size_t)BB * NN * DD];

// ---- attention smem (bytes). K/Q/V pitch 136 halves (272B), P pitch 72 ----
// K resident 34816 | Q 1 buf 17408 | V 2 bufs 34816 | P 18432 | lsum 1KB
// epilogue reuse: O fp16 -> SM_K region, Wp fp16 -> SM_Q region
#define SM_K  0
#define SM_Q  34816
#define SM_V  52224
#define TBUF  17408
#define SM_P  87040
#define SM_LS 105472
#define SM_TOT 106496

// ---- PTX helpers ----
__device__ __forceinline__ uint32_t smem_u32(const void* p) {
    uint32_t a;
    asm("{ .reg .u64 t; cvta.to.shared.u64 t,%1; cvt.u32.u64 %0,t; }" : "=r"(a) : "l"(p));
    return a;
}
__device__ __forceinline__ void ldsmx4(uint32_t* r, uint32_t a) {
    asm volatile("ldmatrix.sync.aligned.m8n8.x4.shared.b16 {%0,%1,%2,%3},[%4];"
                 : "=r"(r[0]), "=r"(r[1]), "=r"(r[2]), "=r"(r[3]) : "r"(a));
}
__device__ __forceinline__ void ldsmx4t(uint32_t* r, uint32_t a) {
    asm volatile("ldmatrix.sync.aligned.m8n8.x4.trans.shared.b16 {%0,%1,%2,%3},[%4];"
                 : "=r"(r[0]), "=r"(r[1]), "=r"(r[2]), "=r"(r[3]) : "r"(a));
}
__device__ __forceinline__ void mma16816(float* c, const uint32_t* a, uint32_t b0, uint32_t b1) {
    asm volatile(
        "mma.sync.aligned.m16n8k16.row.col.f32.f16.f16.f32 "
        "{%0,%1,%2,%3},{%4,%5,%6,%7},{%8,%9},{%0,%1,%2,%3};"
        : "+f"(c[0]), "+f"(c[1]), "+f"(c[2]), "+f"(c[3])
        : "r"(a[0]), "r"(a[1]), "r"(a[2]), "r"(a[3]), "r"(b0), "r"(b1));
}
__device__ __forceinline__ float ex2(float x) {
    float y; asm("ex2.approx.f32 %0,%1;" : "=f"(y) : "f"(x)); return y;
}
__device__ __forceinline__ uint32_t packh2(float lo, float hi) {  // lo -> bits[0:16)
    uint32_t r; asm("cvt.rn.f16x2.f32 %0,%1,%2;" : "=r"(r) : "f"(hi), "f"(lo)); return r;
}
#define CPA16(dst, src) \
    asm volatile("cp.async.cg.shared.global [%0],[%1],16;" :: "r"(dst), "l"(src))
#define CPA_COMMIT() asm volatile("cp.async.commit_group;" ::: "memory")
#define CPA_WAIT0()  asm volatile("cp.async.wait_group 0;" ::: "memory")

// ============================================================================
// Attention + fused output projection. BM=128, 8 warps, 2 CTAs/SM.
// Loop tile: S(jt) | exp->P | sync | cp.async QV(jt+1) | PV(jt) | wait | sync
// Epilogue: O/l -> fp16 smem, Wp -> fp16 smem, 128x128 HMMA, +bias -> out.
// ============================================================================
__global__ void __launch_bounds__(256, 2)
attn_mma(const __half* __restrict__ khg, const __half* __restrict__ vhg,
         const __half* __restrict__ qhg, const float* __restrict__ Wp,
         const float* __restrict__ bp, float* __restrict__ out) {
    extern __shared__ char smem[];
    const uint32_t sb = smem_u32(smem);
    const int tid = threadIdx.x, lane = tid & 31, wid = tid >> 5;
    const int q = lane & 3, lr = lane >> 2;
    const int b = blockIdx.y, row0 = blockIdx.x * BM;

    const __half* kh_b = khg + ((size_t)b * NN + row0) * DD;
    const __half* vh_b = vhg + (size_t)b * NN * DD;
    const __half* qh_b = qhg + (size_t)b * NN * DD;

    const int rg = wid >> 1, cg = wid & 1;   // S: 4x2 warp grid (32x32)
    const int r2 = wid >> 2, c2 = wid & 3;   // PV/proj: 2x4 warp grid (64x32)

    const int rA = (lane & 7) + (lane & 8), cA = (lane & 16) >> 1;   // A/P/V pattern
    const int rB = (lane & 7) + ((lane & 16) >> 1), cB = lane & 8;   // B (Q) pattern

    // ldmatrix bases
    uint32_t aK[2], bQ[2], aP[4], bV[2][2];
    #pragma unroll
    for (int mt = 0; mt < 2; ++mt)
        aK[mt] = sb + SM_K + 2u * ((32 * rg + 16 * mt + rA) * 136 + cA);
    #pragma unroll
    for (int bt = 0; bt < 2; ++bt)
        bQ[bt] = sb + SM_Q + 2u * ((32 * cg + 16 * bt + rB) * 136 + cB);
    #pragma unroll
    for (int mt = 0; mt < 4; ++mt)
        aP[mt] = sb + SM_P + 2u * ((64 * r2 + 16 * mt + rA) * 72 + cA);
    #pragma unroll
    for (int bf = 0; bf < 2; ++bf)
        #pragma unroll
        for (int bt = 0; bt < 2; ++bt)
            bV[bf][bt] = sb + SM_V + bf * TBUF +
                         2u * (rA * 136 + 32 * c2 + 16 * bt + cA);

    // stage K tile (resident during main loop)
    #pragma unroll
    for (int t = 0; t < 8; ++t) {
        int c = tid + (t << 8);
        int r = c >> 4, c16 = c & 15;
        *(uint4*)(smem + SM_K + (uint32_t)(r * 272 + c16 * 16)) =
            *(const uint4*)((const char*)(kh_b + (size_t)r * DD) + c16 * 16);
    }
    // prefetch tile 0 (Q, V buf0)
    #pragma unroll
    for (int t = 0; t < 4; ++t) {
        int c = tid + (t << 8);
        int m = c >> 4, c16 = c & 15;
        uint32_t dof = (uint32_t)(m * 272 + c16 * 16);
        CPA16(sb + SM_Q + dof, (const char*)(qh_b + (size_t)m * DD) + c16 * 16);
        CPA16(sb + SM_V + dof, (const char*)(vh_b + (size_t)m * DD) + c16 * 16);
    }
    CPA_COMMIT();
    CPA_WAIT0();
    __syncthreads();   // K + Q(0) + V(0) visible

    float sO[4][4][4];
    #pragma unroll
    for (int i = 0; i < 4; ++i)
        #pragma unroll
        for (int j = 0; j < 4; ++j) {
            sO[i][j][0] = 0.f; sO[i][j][1] = 0.f; sO[i][j][2] = 0.f; sO[i][j][3] = 0.f;
        }
    float lloc[4] = {0.f, 0.f, 0.f, 0.f};

    for (int jt = 0; jt < NT; ++jt) {
        const int vc = jt & 1;

        // ---- S(jt) = K @ Q^T : 32x32 warp tile, 8 k-steps ----
        float sC[2][4][4];
        #pragma unroll
        for (int i = 0; i < 2; ++i)
            #pragma unroll
            for (int j = 0; j < 4; ++j) {
                sC[i][j][0] = 0.f; sC[i][j][1] = 0.f; sC[i][j][2] = 0.f; sC[i][j][3] = 0.f;
            }
        #pragma unroll
        for (int ks = 0; ks < 8; ++ks) {
            uint32_t kf[2][4], qf[2][4];
            #pragma unroll
            for (int mt = 0; mt < 2; ++mt) ldsmx4(kf[mt], aK[mt] + ks * 32);
            #pragma unroll
            for (int bt = 0; bt < 2; ++bt) ldsmx4(qf[bt], bQ[bt] + ks * 32);
            #pragma unroll
            for (int mt = 0; mt < 2; ++mt)
                #pragma unroll
                for (int nt = 0; nt < 4; ++nt)
                    mma16816(sC[mt][nt], kf[mt],
                             qf[nt >> 1][2 * (nt & 1)], qf[nt >> 1][2 * (nt & 1) + 1]);
        }

        // ---- P(jt) = exp2(S) fp16 -> smem; accumulate row sums ----
        #pragma unroll
        for (int mt = 0; mt < 2; ++mt) {
            int rbase = 32 * rg + 16 * mt + lr;
            #pragma unroll
            for (int nt = 0; nt < 4; ++nt) {
                int col = 32 * cg + 8 * nt + 2 * q;
                float p0 = ex2(sC[mt][nt][0]), p1 = ex2(sC[mt][nt][1]);
                float p2 = ex2(sC[mt][nt][2]), p3 = ex2(sC[mt][nt][3]);
                lloc[2 * mt] += p0 + p1;
                lloc[2 * mt + 1] += p2 + p3;
                *(uint32_t*)(smem + SM_P + 2u * (rbase * 72 + col)) = packh2(p0, p1);
                *(uint32_t*)(smem + SM_P + 2u * ((rbase + 8) * 72 + col)) = packh2(p2, p3);
            }
        }
        __syncthreads();   // P visible; Q(jt) fully consumed

        // prefetch Q(jt+1), V(jt+1) — overlapped with PV below
        if (jt + 1 < NT) {
            const size_t m1 = (size_t)(jt + 1) * BN;
            #pragma unroll
            for (int t = 0; t < 4; ++t) {
                int c = tid + (t << 8);
                int m = c >> 4, c16 = c & 15;
                uint32_t dof = (uint32_t)(m * 272 + c16 * 16);
                CPA16(sb + SM_Q + dof,
                      (const char*)(qh_b + (m1 + m) * DD) + c16 * 16);
                CPA16(sb + SM_V + (vc ^ 1) * TBUF + dof,
                      (const char*)(vh_b + (m1 + m) * DD) + c16 * 16);
            }
            CPA_COMMIT();
        }

        // ---- PV(jt): O += P @ V : 64x32 warp tile, 4 k-steps ----
        #pragma unroll
        for (int ks = 0; ks < 4; ++ks) {
            uint32_t ph[4][4], vf[2][4];
            #pragma unroll
            for (int mt = 0; mt < 4; ++mt) ldsmx4(ph[mt], aP[mt] + ks * 32);
            #pragma unroll
            for (int bt = 0; bt < 2; ++bt) ldsmx4t(vf[bt], bV[vc][bt] + ks * 4352);
            #pragma unroll
            for (int mt = 0; mt < 4; ++mt)
                #pragma unroll
                for (int nt = 0; nt < 4; ++nt)
                    mma16816(sO[mt][nt], ph[mt],
                             vf[nt >> 1][2 * (nt & 1)], vf[nt >> 1][2 * (nt & 1) + 1]);
        }

        if (jt + 1 < NT) CPA_WAIT0();
        __syncthreads();   // PV(jt) done; QV(jt+1) arrived
    }

    // ---- l reduction: quad shfl + cross-colgroup via smem ----
    #pragma unroll
    for (int i = 0; i < 4; ++i) {
        lloc[i] += __shfl_xor_sync(0xffffffffu, lloc[i], 1);
        lloc[i] += __shfl_xor_sync(0xffffffffu, lloc[i], 2);
    }
    float* lsum = (float*)(smem + SM_LS);
    if (q == 0) {
        #pragma unroll
        for (int i = 0; i < 4; ++i) {
            int row = 32 * rg + 16 * (i >> 1) + 8 * (i & 1) + lr;
            lsum[cg * 128 + row] = lloc[i];
        }
    }
    __syncthreads();

    // ---- epilogue part 1: O/l -> fp16 into SM_K (pitch 136); Wp -> SM_Q ----
    #pragma unroll
    for (int mt = 0; mt < 4; ++mt) {
        int ra = 64 * r2 + 16 * mt + lr;
        float inva = 1.0f / (lsum[ra] + lsum[128 + ra]);
        float invb = 1.0f / (lsum[ra + 8] + lsum[128 + ra + 8]);
        #pragma unroll
        for (int nt = 0; nt < 4; ++nt) {
            int col = 32 * c2 + 8 * nt + 2 * q;
            *(uint32_t*)(smem + SM_K + 2u * (ra * 136 + col)) =
                packh2(sO[mt][nt][0] * inva, sO[mt][nt][1] * inva);
            *(uint32_t*)(smem + SM_K + 2u * ((ra + 8) * 136 + col)) =
                packh2(sO[mt][nt][2] * invb, sO[mt][nt][3] * invb);
        }
    }
    #pragma unroll
    for (int it = 0; it < 16; ++it) {   // Wp fp32 -> fp16 (pitch 136), [k][n]
        int f = tid + (it << 8);
        int k = f >> 5, c4 = f & 31;
        float4 v = *(const float4*)(Wp + (size_t)k * 128 + (c4 << 2));
        uint2 h; h.x = packh2(v.x, v.y); h.y = packh2(v.z, v.w);
        *(uint2*)(smem + SM_Q + (uint32_t)(k * 272 + (c4 << 3))) = h;
    }
    __syncthreads();

    // ---- epilogue part 2: out = Onorm @ Wp + bp (128x128 HMMA) ----
    {
        uint32_t aB[4], bB[2];
        #pragma unroll
        for (int mt = 0; mt < 4; ++mt)
            aB[mt] = sb + SM_K + 2u * ((64 * r2 + 16 * mt + rA) * 136 + cA);
        #pragma unroll
        for (int bt = 0; bt < 2; ++bt)
            bB[bt] = sb + SM_Q + 2u * (rA * 136 + 32 * c2 + 16 * bt + cA);

        float acc[4][4][4];
        #pragma unroll
        for (int i = 0; i < 4; ++i)
            #pragma unroll
            for (int j = 0; j < 4; ++j) {
                acc[i][j][0] = 0.f; acc[i][j][1] = 0.f; acc[i][j][2] = 0.f; acc[i][j][3] = 0.f;
            }
        #pragma unroll
        for (int ks = 0; ks < 8; ++ks) {
            uint32_t a[4][4], bf[2][4];
            #pragma unroll
            for (int mt = 0; mt < 4; ++mt) ldsmx4(a[mt], aB[mt] + ks * 32);
            #pragma unroll
            for (int bt = 0; bt < 2; ++bt) ldsmx4t(bf[bt], bB[bt] + ks * 4352);
            #pragma unroll
            for (int mt = 0; mt < 4; ++mt)
                #pragma unroll
                for (int nt = 0; nt < 4; ++nt)
                    mma16816(acc[mt][nt], a[mt],
                             bf[nt >> 1][2 * (nt & 1)], bf[nt >> 1][2 * (nt & 1) + 1]);
        }

        float* ob = out + ((size_t)b * NN + row0) * DD;
        #pragma unroll
        for (int mt = 0; mt < 4; ++mt) {
            int ra = 64 * r2 + 16 * mt + lr;
            #pragma unroll
            for (int nt = 0; nt < 4; ++nt) {
                int col = 32 * c2 + 8 * nt + 2 * q;
                float b0 = bp[col], b1 = bp[col + 1];
                *(float2*)(ob + (size_t)ra * DD + col) =
                    make_float2(acc[mt][nt][0] + b0, acc[mt][nt][1] + b1);
                *(float2*)(ob + (size_t)(ra + 8) * DD + col) =
                    make_float2(acc[mt][nt][2] + b0, acc[mt][nt][3] + b1);
            }
        }
    }
}

// ============================================================================
// fp16 tensor-core kv projection (128x128 CTA tile) + fused Q conversion
// grid (3, M/128): x in {0,1} -> kv cols; x==2 -> Q fp32->fp16 (scaled)
// ============================================================================
__device__ __forceinline__ uint32_t pack_us2(__half a, __half b) {
    return (uint32_t)__half_as_ushort(a) | ((uint32_t)__half_as_ushort(b) << 16);
}

__global__ void __launch_bounds__(256, 2)
gemm16_kv(const float* __restrict__ A, const float* __restrict__ W,
          const float* __restrict__ bias, const float* __restrict__ qg,
          __half* __restrict__ kh, __half* __restrict__ vh,
          __half* __restrict__ qh) {
    if (blockIdx.x == 2) {   // fused qconv: 128 rows of Q per y-block
        const size_t base = (size_t)blockIdx.y * (128 * 128 / 4);
        const float4* src = (const float4*)qg + base;
        __half2* dst = (__half2*)qh + base * 2;
        #pragma unroll
        for (int t = 0; t < 16; ++t) {
            int f = threadIdx.x + (t << 8);
            float4 v = src[f];
            dst[2 * f]     = __floats2half2_rn(v.x * QS, v.y * QS);
            dst[2 * f + 1] = __floats2half2_rn(v.z * QS, v.w * QS);
        }
        return;
    }

    extern __shared__ char smg[];
    const uint32_t sb = smem_u32(smg);
    const int tid = threadIdx.x, lane = tid & 31, wid = tid >> 5;
    const int q = lane & 3, lr = lane >> 2;
    const int rw = wid >> 2, cw = wid & 3;
    const int row0 = blockIdx.y * 128, col0 = blockIdx.x * 128;

    #pragma unroll
    for (int it = 0; it < 16; ++it) {
        int f = tid + (it << 8);
        int r = f >> 5, c4 = f & 31;
        float4 v = *(const float4*)(A + (size_t)(row0 + r) * 128 + (c4 << 2));
        uint2 h; h.x = packh2(v.x, v.y); h.y = packh2(v.z, v.w);
        *(uint2*)(smg + (uint32_t)(r * 272 + (c4 << 3))) = h;
    }
    #pragma unroll
    for (int it = 0; it < 16; ++it) {
        int f = tid + (it << 8);
        int k = f >> 5, c4 = f & 31;
        float4 v = *(const float4*)(W + (size_t)k * 256 + col0 + (c4 << 2));
        uint2 h; h.x = packh2(v.x, v.y); h.y = packh2(v.z, v.w);
        *(uint2*)(smg + 34816 + (uint32_t)(k * 272 + (c4 << 3))) = h;
    }
    __syncthreads();

    const int rA = (lane & 7) + (lane & 8), cA = (lane & 16) >> 1;
    uint32_t aBase[4], bBase[2];
    #pragma unroll
    for (int mt = 0; mt < 4; ++mt)
        aBase[mt] = sb + 2u * ((64 * rw + 16 * mt + rA) * 136 + cA);
    #pragma unroll
    for (int bt = 0; bt < 2; ++bt)
        bBase[bt] = sb + 34816 + 2u * (rA * 136 + 32 * cw + 16 * bt + cA);

    float acc[4][4][4];
    #pragma unroll
    for (int i = 0; i < 4; ++i)
        #pragma unroll
        for (int j = 0; j < 4; ++j) {
            acc[i][j][0] = 0.f; acc[i][j][1] = 0.f; acc[i][j][2] = 0.f; acc[i][j][3] = 0.f;
        }
    #pragma unroll
    for (int ks = 0; ks < 8; ++ks) {
        uint32_t a[4][4], bf[2][4];
        #pragma unroll
        for (int mt = 0; mt < 4; ++mt) ldsmx4(a[mt], aBase[mt] + ks * 32);
        #pragma unroll
        for (int bt = 0; bt < 2; ++bt) ldsmx4t(bf[bt], bBase[bt] + ks * 4352);
        #pragma unroll
        for (int mt = 0; mt < 4; ++mt)
            #pragma unroll
            for (int nt = 0; nt < 4; ++nt)
                mma16816(acc[mt][nt], a[mt],
                         bf[nt >> 1][2 * (nt & 1)], bf[nt >> 1][2 * (nt & 1) + 1]);
    }

    __half* dh = (col0 == 0) ? kh : vh;
    #pragma unroll
    for (int mt = 0; mt < 4; ++mt) {
        int r = row0 + 64 * rw + 16 * mt + lr;
        #pragma unroll
        for (int nt = 0; nt < 4; ++nt) {
            int col = 32 * cw + 8 * nt + 2 * q;
            float b0 = bias[col0 + col], b1 = bias[col0 + col + 1];
            *(uint32_t*)(dh + (size_t)r * 128 + col) = pack_us2(
                __float2half_rn(acc[mt][nt][0] + b0), __float2half_rn(acc[mt][nt][1] + b1));
            *(uint32_t*)(dh + (size_t)(r + 8) * 128 + col) = pack_us2(
                __float2half_rn(acc[mt][nt][2] + b0), __float2half_rn(acc[mt][nt][3] + b1));
        }
    }
}

// ============================================================================
extern "C" void kernel_launch(void* const* d_in, const int* in_sizes, int n_in,
                              void* d_out, int out_size) {
    const float* x   = (const float*)d_in[0];
    const float* qg  = (const float*)d_in[1];
    const float* Wkv = (const float*)d_in[2];
    const float* bkv = (const float*)d_in[3];
    const float* Wp  = (const float*)d_in[4];
    const float* bp  = (const float*)d_in[5];
    float* out = (float*)d_out;

    __half *khp, *vhp, *qhp;
    cudaGetSymbolAddress((void**)&khp, g_kh);
    cudaGetSymbolAddress((void**)&vhp, g_vh);
    cudaGetSymbolAddress((void**)&qhp, g_qh);

    const int M = BB * NN;
    const int gsm = 2 * 128 * 272;  // 69632 B

    cudaFuncSetAttribute(gemm16_kv,
                         cudaFuncAttributeMaxDynamicSharedMemorySize, gsm);
    cudaFuncSetAttribute(attn_mma,
                         cudaFuncAttributeMaxDynamicSharedMemorySize, SM_TOT);

    gemm16_kv<<<dim3(3, M / 128), 256, gsm>>>(x, Wkv, bkv, qg, khp, vhp, qhp);
    attn_mma<<<dim3(NN / BM, BB), 256, SM_TOT>>>(khp, vhp, qhp, Wp, bp, out);
}